// round 1
// baseline (speedup 1.0000x reference)
#include <cuda_runtime.h>
#include <cstdint>

// Problem constants (fixed shapes for this problem)
#define T_LEN 4096
#define B_LEN 4096

// LUT config: log2-spaced piecewise-linear table of
//   g(s) = (1/sqrt(2pi)) * int_{-5}^{5} (1 - tanh(sqrt(s)*z)^2) exp(-z^2/2) dz
// indexed directly by float bits of s. 64 bins/octave, s in [2^-16, 2^8).
#define NLUT 1536                 // 24 octaves * 64 bins
#define NB   (NLUT + 1)           // bin boundaries
#define BASE_BITS 0x37800000u     // float bits of 2^-16 (exponent 111)
#define BASE_OFF  56832u          // (BASE_BITS >> 14) = 111*64*8
#define EPS_S 1.52587890625e-05f  // 2^-16, added to u^2 so s >= 2^-16 always

__device__ float  g_bound[NB];
__device__ float2 g_lut[NLUT];

// ---------------------------------------------------------------------------
// Kernel 1: boundary values of g via composite Simpson on [0,5] (even
// integrand -> x2), n=2048 intervals, tanhf/expf in f32, double accumulation.
// Accuracy vs the reference's GL-128 (which is itself ~exact for delta<=8):
// abs err ~1e-7 at delta=8, ~2e-6 at the LUT top (delta=16, never reached).
// One warp per boundary.
// ---------------------------------------------------------------------------
__global__ void build_bounds_kernel() {
    int j = blockIdx.x;            // 0 .. NB-1
    int lane = threadIdx.x;        // 32 threads
    unsigned bits = BASE_BITS + ((unsigned)j << 17);
    float s = __uint_as_float(bits);
    float delta = sqrtf(s);

    const int   n = 2048;
    const float h = 5.0f / (float)n;
    double acc = 0.0;
    for (int i = lane; i <= n; i += 32) {
        float z = h * (float)i;
        float t = tanhf(delta * z);
        float f = (1.0f - t * t) * expf(-0.5f * z * z);
        float coef = (i == 0 || i == n) ? 1.0f : ((i & 1) ? 4.0f : 2.0f);
        acc += (double)(f * coef);
    }
    #pragma unroll
    for (int o = 16; o; o >>= 1)
        acc += __shfl_down_sync(0xffffffffu, acc, o);
    if (lane == 0) {
        double integ = acc * ((double)h / 3.0);        // int_0^5
        double g = 2.0 * integ * 0.3989422804014327;   // * 1/sqrt(2pi), even
        g_bound[j] = (float)g;
    }
}

// ---------------------------------------------------------------------------
// Kernel 2: pack (value, slope) pairs; slope pre-scaled by 2^-17 so the
// runtime frac is the raw low-17 mantissa bits converted to float.
// ---------------------------------------------------------------------------
__global__ void build_lut_kernel() {
    int i = blockIdx.x * blockDim.x + threadIdx.x;
    if (i < NLUT) {
        float a = g_bound[i];
        float b = g_bound[i + 1];
        g_lut[i] = make_float2(a, (b - a) * (1.0f / 131072.0f));
    }
}

// ---------------------------------------------------------------------------
// Main scan kernel: one thread per batch row, one warp (32 rows) per block,
// 128 blocks -> ~1 block per SM. Latency-bound on the per-step RAW chain:
//   FFMA(s) -> FMNMX(clamp) -> SHF -> LOP3 -> LDS.64 -> FFMA(interp) -> FFMA(k)
// u is prefetched via cp.async into double-buffered transposed smem tiles.
// ---------------------------------------------------------------------------
__device__ __forceinline__ void prefetch_tile(const float* __restrict__ u,
                                              int b0, int tile,
                                              unsigned sbase, int lane) {
    const float* src = u + (size_t)b0 * T_LEN + (size_t)tile * 32 + lane;
    #pragma unroll
    for (int r = 0; r < 32; ++r) {
        unsigned d = sbase + (unsigned)((r * 33 + lane) * 4);
        const float* s = src + (size_t)r * T_LEN;
        asm volatile("cp.async.ca.shared.global [%0], [%1], 4;" :: "r"(d), "l"(s));
    }
}

__global__ __launch_bounds__(32, 1)
void scan_kernel(const float* __restrict__ u, float* __restrict__ out) {
    __shared__ float2 lut_s[NLUT];
    __shared__ float  u_s[2][32 * 33];

    int lane = threadIdx.x;
    int b0 = blockIdx.x * 32;
    int b  = b0 + lane;

    // Stage LUT into shared (float4 copies)
    {
        const float4* src = (const float4*)g_lut;   // NLUT*8B / 16 = 768
        float4* dst = (float4*)lut_s;
        #pragma unroll 4
        for (int i = lane; i < NLUT / 2; i += 32) dst[i] = src[i];
    }

    unsigned us_base0 = (unsigned)__cvta_generic_to_shared(&u_s[0][0]);
    unsigned us_base1 = (unsigned)__cvta_generic_to_shared(&u_s[1][0]);
    unsigned lut_lm   = (unsigned)__cvta_generic_to_shared(lut_s) - BASE_OFF;

    // Prefetch first two u tiles
    prefetch_tile(u, b0, 0, us_base0, lane);
    asm volatile("cp.async.commit_group;" ::: "memory");
    prefetch_tile(u, b0, 1, us_base1, lane);
    asm volatile("cp.async.commit_group;" ::: "memory");

    float* zrow = out + (size_t)b * (T_LEN + 1);
    zrow[0] = 0.0f;
    float* zw = zrow + 1;

    __syncwarp();   // LUT visible to all lanes

    float k = 0.0f, v = 0.0f;
    const float SMAX = __uint_as_float(0x437FFFFFu);  // just below 256

    for (int tile = 0; tile < T_LEN / 32; ++tile) {
        asm volatile("cp.async.wait_group 1;" ::: "memory");
        __syncwarp();

        const float* ut = &u_s[tile & 1][lane * 33];
        float* zt = zw + tile * 32;

        #pragma unroll
        for (int c = 0; c < 32; ++c) {
            float uin = ut[c];
            // v-chain (independent of k): v <- v + (u - v)*0.2
            v = fmaf(0.2f, uin, 0.8f * v);
            float w  = 0.52f * v;             // 2.6 * g * v * 0.2 coefficient
            float q  = fmaf(0.28f, k, w);     // g multiplier, parallel to lookup
            float kk = 0.8f * k;              // parallel to lookup
            float uu = fmaf(uin, uin, EPS_S); // s >= 2^-16 guaranteed
            float s  = fmaf(k, k, uu);        // chain start
            s = fminf(s, SMAX);               // high clamp (also absorbs NaN)
            unsigned bits = __float_as_uint(s);
            unsigned addr = lut_lm + ((bits >> 14) & 0x1FFF8u);
            float a0, a1;
            asm volatile("ld.shared.v2.f32 {%0, %1}, [%2];"
                         : "=f"(a0), "=f"(a1) : "r"(addr));
            float fr = __uint2float_rn(bits & 0x1FFFFu);  // parallel with LDS
            float g  = fmaf(fr, a1, a0);
            k = fmaf(g, q, kk);
            zt[c] = 2.1f * k;                 // SIG_MW * k
        }

        __syncwarp();  // all lanes done reading buffer before overwrite
        if (tile < T_LEN / 32 - 2)
            prefetch_tile(u, b0, tile + 2, (tile & 1) ? us_base1 : us_base0, lane);
        asm volatile("cp.async.commit_group;" ::: "memory");  // keep group count aligned
    }
}

// ---------------------------------------------------------------------------
extern "C" void kernel_launch(void* const* d_in, const int* in_sizes, int n_in,
                              void* d_out, int out_size) {
    const float* u = (const float*)d_in[0];
    float* out = (float*)d_out;
    (void)in_sizes; (void)n_in; (void)out_size;

    build_bounds_kernel<<<NB, 32>>>();
    build_lut_kernel<<<(NLUT + 255) / 256, 256>>>();
    scan_kernel<<<B_LEN / 32, 32>>>(u, out);
}